// round 16
// baseline (speedup 1.0000x reference)
#include <cuda_runtime.h>
#include <cuda_fp16.h>
#include <math.h>
#include <stdint.h>

// ---------------------------------------------------------------------------
// RPN round 16: Winograd F(4x4,3x3) split-fp16 HMMA, fused producer/consumer
// with SPLIT-K4 GEMM jobs (short blocks -> fine-grained overlap).
//  grid: [112 xtrans][ per mtile: 256 wtrans | 144 gemm(36pos x 4ksl) ] x16
// ---------------------------------------------------------------------------

#define NPIX  784
#define NT7   7
#define NTIL  49
#define NTP   56
#define NPOS  36
#define KDIM  2048
#define KC    64
#define NCHH  8                // chunks per K-slice (K=512)
#define NKSL  4
#define TM    128
#define TN    56
#define NSTG  2
#define A_BYTES (TM * 128)
#define B_BYTES (TN * 128)
#define STG_SZ  (2 * A_BYTES + 2 * B_BYTES)   // 47104
#define CONV_SMEM (NSTG * STG_SZ + 1024)      // 95232
#define OFF_AH  0
#define OFF_AL  A_BYTES
#define OFF_BH  (2 * A_BYTES)
#define OFF_BL  (2 * A_BYTES + B_BYTES)

#define USTRIDE (2048 * 2048)
#define VSTRIDE (NTP * 2048)
#define MSTRIDE (2048 * NTP)

#define NBX  112
#define GRPP 256
#define GRPC (NPOS * NKSL)     // 144
#define GRP  (GRPP + GRPC)     // 400
#define NGRID (NBX + 16 * GRP) // 6512

__device__ __half g_Uhi[NPOS * USTRIDE];
__device__ __half g_Ulo[NPOS * USTRIDE];
__device__ __half g_Vhi[NPOS * VSTRIDE];
__device__ __half g_Vlo[NPOS * VSTRIDE];
__device__ float  g_m[NKSL][NPOS * MSTRIDE];
__device__ float  g_h[2048 * NPIX];
__device__ float  g_ht[NPIX * 2048];
__device__ float  g_head[45 * NPIX];
__device__ int    g_flag_x;
__device__ int    g_flag_w[16];

#define SWZ(o) ((uint32_t)(o) ^ ((((uint32_t)(o)) >> 3) & 0x70u))

__device__ __forceinline__ uint32_t smem_u32(const void* p) {
    uint32_t a;
    asm("{ .reg .u64 t; cvta.to.shared.u64 t, %1; cvt.u32.u64 %0, t; }"
        : "=r"(a) : "l"(p));
    return a;
}
__device__ __forceinline__ void cpa16(uint32_t dst, const void* src) {
    asm volatile("cp.async.cg.shared.global [%0], [%1], 16;"
                 :: "r"(dst), "l"(src) : "memory");
}
__device__ __forceinline__ void ldsm4(uint32_t* r, uint32_t addr) {
    asm volatile("ldmatrix.sync.aligned.m8n8.x4.shared.b16 {%0,%1,%2,%3}, [%4];"
                 : "=r"(r[0]), "=r"(r[1]), "=r"(r[2]), "=r"(r[3]) : "r"(addr));
}
__device__ __forceinline__ void ldsm2(uint32_t* r, uint32_t addr) {
    asm volatile("ldmatrix.sync.aligned.m8n8.x2.shared.b16 {%0,%1}, [%2];"
                 : "=r"(r[0]), "=r"(r[1]) : "r"(addr));
}
__device__ __forceinline__ void mma16816(float* d, const uint32_t* a, const uint32_t* b) {
    asm volatile(
        "mma.sync.aligned.m16n8k16.row.col.f32.f16.f16.f32 "
        "{%0,%1,%2,%3}, {%4,%5,%6,%7}, {%8,%9}, {%0,%1,%2,%3};"
        : "+f"(d[0]), "+f"(d[1]), "+f"(d[2]), "+f"(d[3])
        : "r"(a[0]), "r"(a[1]), "r"(a[2]), "r"(a[3]), "r"(b[0]), "r"(b[1]));
}
__device__ __forceinline__ ushort hi_part(float v, float& rem) {
    __half h = __float2half_rn(v);
    rem = v - __half2float(h);
    return *(ushort*)&h;
}

// ------------------------- role: weight transform --------------------------
__device__ void wtrans_role(const float* __restrict__ W, int b) {
    const int q = b * 256 + threadIdx.x;
    const int t0 = q * 4;

    float f[36];
    {
        const float4* w4 = (const float4*)(W + (size_t)t0 * 9);
        #pragma unroll
        for (int k = 0; k < 9; k++) {
            float4 v = __ldg(&w4[k]);
            f[4 * k + 0] = v.x; f[4 * k + 1] = v.y;
            f[4 * k + 2] = v.z; f[4 * k + 3] = v.w;
        }
    }

    const float c6 = 1.f / 6.f, c12 = 1.f / 12.f, c24 = 1.f / 24.f;
    #pragma unroll
    for (int i = 0; i < 6; i++) {
        ushort hi6[6][4], lo6[6][4];
        #pragma unroll
        for (int j = 0; j < 4; j++) {
            const float* g = f + j * 9;
            float tc[3];
            #pragma unroll
            for (int cc = 0; cc < 3; cc++) {
                float a = g[cc], bb = g[3 + cc], d = g[6 + cc];
                tc[cc] = (i == 0) ? 0.25f * a
                       : (i == 1) ? -c6 * (a + bb + d)
                       : (i == 2) ? c6 * (-a + bb - d)
                       : (i == 3) ? c24 * a + c12 * bb + c6 * d
                       : (i == 4) ? c24 * a - c12 * bb + c6 * d
                                  : d;
            }
            float u[6];
            u[0] = 0.25f * tc[0];
            u[1] = -c6 * (tc[0] + tc[1] + tc[2]);
            u[2] = c6 * (-tc[0] + tc[1] - tc[2]);
            u[3] = c24 * tc[0] + c12 * tc[1] + c6 * tc[2];
            u[4] = c24 * tc[0] - c12 * tc[1] + c6 * tc[2];
            u[5] = tc[2];
            #pragma unroll
            for (int cc = 0; cc < 6; cc++) {
                float rem;
                hi6[cc][j] = hi_part(u[cc], rem);
                __half lo = __float2half_rn(rem);
                lo6[cc][j] = *(ushort*)&lo;
            }
        }
        #pragma unroll
        for (int cc = 0; cc < 6; cc++) {
            int p = 6 * i + cc;
            *(uint2*)(g_Uhi + (size_t)p * USTRIDE + t0) = *(uint2*)hi6[cc];
            *(uint2*)(g_Ulo + (size_t)p * USTRIDE + t0) = *(uint2*)lo6[cc];
        }
    }

    __syncthreads();
    if (threadIdx.x == 0) {
        __threadfence();
        atomicAdd(&g_flag_w[b >> 8], 1);
    }
}

// -------------------------- role: input transform --------------------------
__device__ void xtrans_role(const float* __restrict__ X, int b) {
    const int q = b * 256 + threadIdx.x;
    const int t0 = q * 4;
    const int tile = t0 >> 11;
    const int ic0 = t0 & 2047;

    if (tile >= NTIL) {
        #pragma unroll
        for (int p = 0; p < 36; p++) {
            *(uint2*)(g_Vhi + (size_t)p * VSTRIDE + t0) = make_uint2(0u, 0u);
            *(uint2*)(g_Vlo + (size_t)p * VSTRIDE + t0) = make_uint2(0u, 0u);
        }
    } else {
        const int ti = tile / NT7, tj = tile - ti * NT7;
        ushort dhi[36][4], dlo[36][4];
        #pragma unroll
        for (int j = 0; j < 4; j++) {
            const float* xp = X + (size_t)(ic0 + j) * NPIX;
            float d[6][6];
            #pragma unroll
            for (int r = 0; r < 6; r++) {
                int yy = 4 * ti - 1 + r;
                #pragma unroll
                for (int cq = 0; cq < 6; cq++) {
                    int xx = 4 * tj - 1 + cq;
                    d[r][cq] = ((unsigned)yy < 28u && (unsigned)xx < 28u)
                               ? __ldg(&xp[yy * 28 + xx]) : 0.f;
                }
            }
            float T[6][6];
            #pragma unroll
            for (int c = 0; c < 6; c++) {
                T[0][c] = 4.f * d[0][c] - 5.f * d[2][c] + d[4][c];
                T[1][c] = -4.f * d[1][c] - 4.f * d[2][c] + d[3][c] + d[4][c];
                T[2][c] = 4.f * d[1][c] - 4.f * d[2][c] - d[3][c] + d[4][c];
                T[3][c] = -2.f * d[1][c] - d[2][c] + 2.f * d[3][c] + d[4][c];
                T[4][c] = 2.f * d[1][c] - d[2][c] - 2.f * d[3][c] + d[4][c];
                T[5][c] = 4.f * d[1][c] - 5.f * d[3][c] + d[5][c];
            }
            #pragma unroll
            for (int i = 0; i < 6; i++) {
                float v[6];
                v[0] = 4.f * T[i][0] - 5.f * T[i][2] + T[i][4];
                v[1] = -4.f * T[i][1] - 4.f * T[i][2] + T[i][3] + T[i][4];
                v[2] = 4.f * T[i][1] - 4.f * T[i][2] - T[i][3] + T[i][4];
                v[3] = -2.f * T[i][1] - T[i][2] + 2.f * T[i][3] + T[i][4];
                v[4] = 2.f * T[i][1] - T[i][2] - 2.f * T[i][3] + T[i][4];
                v[5] = 4.f * T[i][1] - 5.f * T[i][3] + T[i][5];
                #pragma unroll
                for (int cc = 0; cc < 6; cc++) {
                    float rem;
                    dhi[6 * i + cc][j] = hi_part(v[cc], rem);
                    __half lo = __float2half_rn(rem);
                    dlo[6 * i + cc][j] = *(ushort*)&lo;
                }
            }
        }
        #pragma unroll
        for (int p = 0; p < 36; p++) {
            *(uint2*)(g_Vhi + (size_t)p * VSTRIDE + t0) = *(uint2*)dhi[p];
            *(uint2*)(g_Vlo + (size_t)p * VSTRIDE + t0) = *(uint2*)dlo[p];
        }
    }

    __syncthreads();
    if (threadIdx.x == 0) {
        __threadfence();
        atomicAdd(&g_flag_x, 1);
    }
}

// ------------------------------ role: GEMM ---------------------------------
__device__ void gemm_role(int mtile, int ps, char* smraw) {
    uintptr_t basep = ((uintptr_t)smraw + 1023) & ~(uintptr_t)1023;
    const uint32_t smb = smem_u32((void*)basep);

    const int tid  = threadIdx.x;
    const int wid  = tid >> 5;
    const int lane = tid & 31;
    const int m0   = mtile * TM;
    const int pos  = ps >> 2;
    const int ksl  = ps & 3;
    const int kbase = ksl * (NCHH * KC);

    if (tid == 0) {
        while (atomicAdd(&g_flag_x, 0) < NBX) __nanosleep(256);
        while (atomicAdd(&g_flag_w[mtile], 0) < GRPP) __nanosleep(256);
        __threadfence();
    }
    __syncthreads();

    const __half* Ahi = g_Uhi + (size_t)pos * USTRIDE;
    const __half* Alo = g_Ulo + (size_t)pos * USTRIDE;
    const __half* Bhi = g_Vhi + (size_t)pos * VSTRIDE;
    const __half* Blo = g_Vlo + (size_t)pos * VSTRIDE;

    uint32_t aoff, boff[7];
    {
        int arow = wid * 16 + (lane & 15);
        int acol = (lane >> 4) * 16;
        aoff = SWZ(arow * 128 + acol);
        int bi = lane & 15;
        #pragma unroll
        for (int nt = 0; nt < 7; nt++)
            boff[nt] = SWZ((nt * 8 + (bi & 7)) * 128 + ((bi >> 3) & 1) * 16);
    }

    float acc[7][4];
    #pragma unroll
    for (int nt = 0; nt < 7; nt++)
        #pragma unroll
        for (int i = 0; i < 4; i++) acc[nt][i] = 0.f;

    auto load_stage = [&](int it) {
        const int stg = it % NSTG;
        const uint32_t sb = smb + stg * STG_SZ;
        const int kc = kbase + it * KC;
        for (int q = tid; q < 1024; q += 256) {
            int r = q >> 3, c = q & 7;
            uint32_t so = SWZ(r * 128 + c * 16);
            size_t go = (size_t)(m0 + r) * KDIM + kc + c * 8;
            cpa16(sb + OFF_AH + so, Ahi + go);
            cpa16(sb + OFF_AL + so, Alo + go);
        }
        for (int q = tid; q < 448; q += 256) {
            int r = q >> 3, c = q & 7;
            uint32_t so = SWZ(r * 128 + c * 16);
            size_t go = (size_t)r * KDIM + kc + c * 8;
            cpa16(sb + OFF_BH + so, Bhi + go);
            cpa16(sb + OFF_BL + so, Blo + go);
        }
    };

    load_stage(0);
    asm volatile("cp.async.commit_group;" ::: "memory");

    for (int c = 0; c < NCHH; ++c) {
        if (c > 0) __syncthreads();
        if (c + 1 < NCHH) {
            load_stage(c + 1);
            asm volatile("cp.async.commit_group;" ::: "memory");
            asm volatile("cp.async.wait_group 1;" ::: "memory");
        } else {
            asm volatile("cp.async.wait_group 0;" ::: "memory");
        }
        __syncthreads();

        const uint32_t sb = smb + (c % NSTG) * STG_SZ;
        #pragma unroll
        for (int kk = 0; kk < 4; kk++) {
            const uint32_t kd = kk * 32;
            uint32_t ah[4], al[4], bh[7][2], bl[7][2];
            ldsm4(ah, sb + OFF_AH + (aoff ^ kd));
            ldsm4(al, sb + OFF_AL + (aoff ^ kd));
            #pragma unroll
            for (int nt = 0; nt < 7; nt++) {
                ldsm2(bh[nt], sb + OFF_BH + (boff[nt] ^ kd));
                ldsm2(bl[nt], sb + OFF_BL + (boff[nt] ^ kd));
            }
            #pragma unroll
            for (int nt = 0; nt < 7; nt++) {
                mma16816(acc[nt], ah, bh[nt]);
                mma16816(acc[nt], ah, bl[nt]);
                mma16816(acc[nt], al, bh[nt]);
            }
        }
    }

    const int l4 = lane >> 2;
    const int l2 = (lane & 3) * 2;
    float* mdst = g_m[ksl] + (size_t)pos * MSTRIDE;
    const int ocA = m0 + wid * 16 + l4;
    const int ocB = ocA + 8;
    #pragma unroll
    for (int nt = 0; nt < 7; nt++) {
        int col = nt * 8 + l2;
        float2 vA, vB;
        vA.x = acc[nt][0]; vA.y = acc[nt][1];
        vB.x = acc[nt][2]; vB.y = acc[nt][3];
        *(float2*)(mdst + (size_t)ocA * NTP + col) = vA;
        *(float2*)(mdst + (size_t)ocB * NTP + col) = vB;
    }
}

// ------------------------------ fused kernel -------------------------------
__global__ __launch_bounds__(256, 2) void fused_kernel(
    const float* __restrict__ W, const float* __restrict__ X)
{
    extern __shared__ char smraw[];
    int bx = blockIdx.x;
    if (bx < NBX) { xtrans_role(X, bx); return; }
    int rem = bx - NBX;
    int g = rem / GRP, r = rem - g * GRP;
    if (r < GRPP) wtrans_role(W, g * GRPP + r);
    else          gemm_role(g, r - GRPP, smraw);
}

__global__ void reset_kernel() {
    if (threadIdx.x == 0) g_flag_x = 0;
    if (threadIdx.x < 16) g_flag_w[threadIdx.x] = 0;
}

// ------------------- inverse transform: y = A^T m A + bias, relu -----------
__global__ __launch_bounds__(256) void itrans_kernel(const float* __restrict__ CB) {
    int t = blockIdx.x * blockDim.x + threadIdx.x;
    if (t >= 2048 * NTIL) return;
    int oc = t / NTIL;
    int tile = t - oc * NTIL;
    int ti = tile / NT7, tj = tile - ti * NT7;

    float m[36];
    #pragma unroll
    for (int p = 0; p < 36; p++) {
        size_t off = (size_t)p * MSTRIDE + (size_t)oc * NTP + tile;
        m[p] = (g_m[0][off] + g_m[1][off]) + (g_m[2][off] + g_m[3][off]);
    }

    float T[4][6];
    #pragma unroll
    for (int c = 0; c < 6; c++) {
        float m0 = m[c], m1 = m[6 + c], m2 = m[12 + c];
        float m3 = m[18 + c], m4 = m[24 + c], m5 = m[30 + c];
        T[0][c] = m0 + m1 + m2 + m3 + m4;
        T[1][c] = m1 - m2 + 2.f * (m3 - m4);
        T[2][c] = m1 + m2 + 4.f * (m3 + m4);
        T[3][c] = m1 - m2 + 8.f * (m3 - m4) + m5;
    }

    float bias = __ldg(&CB[oc]);
    float* hp = g_h + (size_t)oc * NPIX;
    int oy = 4 * ti, ox = 4 * tj;
    #pragma unroll
    for (int i = 0; i < 4; i++) {
        float t0 = T[i][0], t1 = T[i][1], t2 = T[i][2];
        float t3 = T[i][3], t4 = T[i][4], t5 = T[i][5];
        float y0 = t0 + t1 + t2 + t3 + t4;
        float y1 = t1 - t2 + 2.f * (t3 - t4);
        float y2 = t1 + t2 + 4.f * (t3 + t4);
        float y3 = t1 - t2 + 8.f * (t3 - t4) + t5;
        hp[(oy + i) * 28 + ox + 0] = fmaxf(y0 + bias, 0.f);
        hp[(oy + i) * 28 + ox + 1] = fmaxf(y1 + bias, 0.f);
        hp[(oy + i) * 28 + ox + 2] = fmaxf(y2 + bias, 0.f);
        hp[(oy + i) * 28 + ox + 3] = fmaxf(y3 + bias, 0.f);
    }
}

// --------------------- transpose g_h[ch][pix] -> g_ht[pix][ch] -------------
__global__ void transpose_kernel() {
    __shared__ float ts[32][33];
    int cb = blockIdx.x * 32;
    int pb = blockIdx.y * 32;
    int tx = threadIdx.x, ty = threadIdx.y;
    #pragma unroll
    for (int j = 0; j < 4; j++) {
        int ch = cb + ty + j * 8;
        int p = pb + tx;
        if (p < NPIX) ts[ty + j * 8][tx] = g_h[(size_t)ch * NPIX + p];
    }
    __syncthreads();
    #pragma unroll
    for (int j = 0; j < 4; j++) {
        int p = pb + ty + j * 8;
        int ch = cb + tx;
        if (p < NPIX) g_ht[(size_t)p * 2048 + ch] = ts[tx][ty + j * 8];
    }
}

// ------------------------------- heads -------------------------------------
__global__ __launch_bounds__(256) void heads_kernel(
    const float* __restrict__ reg_w, const float* __restrict__ reg_b,
    const float* __restrict__ cls_w, const float* __restrict__ cls_b)
{
    const int lane = threadIdx.x & 31;
    const int warp = threadIdx.x >> 5;
    const int p = blockIdx.x * 8 + warp;

    float4 hv[16];
    #pragma unroll
    for (int j = 0; j < 16; j++)
        hv[j] = __ldg((const float4*)(g_ht + (size_t)p * 2048 + lane * 4 + 128 * j));

    #pragma unroll 1
    for (int o = 0; o < 45; o++) {
        const float* w = (o < 36) ? (reg_w + o * 2048) : (cls_w + (o - 36) * 2048);
        float s = 0.f;
        #pragma unroll
        for (int j = 0; j < 16; j++) {
            float4 wq = __ldg((const float4*)(w + lane * 4 + 128 * j));
            s += hv[j].x * wq.x + hv[j].y * wq.y + hv[j].z * wq.z + hv[j].w * wq.w;
        }
        #pragma unroll
        for (int off = 16; off > 0; off >>= 1) s += __shfl_xor_sync(0xffffffffu, s, off);
        if (lane == 0) {
            float b = (o < 36) ? __ldg(&reg_b[o]) : __ldg(&cls_b[o - 36]);
            g_head[o * NPIX + p] = 1.f / (1.f + expf(-(s + b)));
        }
    }
}

// ------------------------- scan + gather (fused) ---------------------------
__device__ __forceinline__ bool anchor_valid(int j) {
    int a = j % 9, p = j / 9;
    int y = p / 28, x = p % 28;
    double scale = (a / 3 == 0) ? 64.0 : (a / 3 == 1) ? 128.0 : 256.0;
    double ratio = (a % 3 == 0) ? 0.5 : (a % 3 == 1) ? 1.0 : 2.0;
    double hh = scale / sqrt(ratio) / 448.0;
    double ww = scale * sqrt(ratio) / 448.0;
    double cy = ((double)y + 0.5) / 28.0;
    double cx = ((double)x + 0.5) / 28.0;
    double y1 = cy - hh / 2.0, x1 = cx - ww / 2.0;
    double y2 = cy + hh / 2.0, x2 = cx + ww / 2.0;
    return (y1 > 0.0) && (x1 > 0.0) && (y2 < 28.0) && (x2 < 28.0);
}

__global__ void scan_gather_kernel(float* __restrict__ out) {
    __shared__ int s[1024];
    const int tid = threadIdx.x;
    const int base = tid * 7;
    int f[7];
    int cnt = 0;
    #pragma unroll
    for (int i = 0; i < 7; i++) {
        int j = base + i;
        f[i] = (j < 7056 && anchor_valid(j)) ? 1 : 0;
        cnt += f[i];
    }
    s[tid] = cnt;
    __syncthreads();
    for (int off = 1; off < 1024; off <<= 1) {
        int v = s[tid];
        int add = (tid >= off) ? s[tid - off] : 0;
        __syncthreads();
        s[tid] = v + add;
        __syncthreads();
    }
    int pos = s[tid] - cnt;
    #pragma unroll
    for (int i = 0; i < 7; i++) {
        int j = base + i;
        if (j < 7056 && f[i]) {
            int a = j / NPIX, p = j % NPIX;
            float cls = g_head[(36 + a) * NPIX + p];
            float k = (cls > 0.9f) ? 1.f : 0.f;
            #pragma unroll
            for (int c = 0; c < 4; c++)
                out[pos * 4 + c] = g_head[(c * 9 + a) * NPIX + p] * k;
            pos++;
        }
    }
}

// ---------------------------------------------------------------------------
extern "C" void kernel_launch(void* const* d_in, const int* in_sizes, int n_in,
                              void* d_out, int out_size)
{
    const float* x      = (const float*)d_in[0];
    const float* conv_w = (const float*)d_in[1];
    const float* conv_b = (const float*)d_in[2];
    const float* reg_w  = (const float*)d_in[3];
    const float* reg_b  = (const float*)d_in[4];
    const float* cls_w  = (const float*)d_in[5];
    const float* cls_b  = (const float*)d_in[6];
    float* out = (float*)d_out;

    cudaFuncSetAttribute(fused_kernel,
                         cudaFuncAttributeMaxDynamicSharedMemorySize, CONV_SMEM);

    reset_kernel<<<1, 32>>>();
    fused_kernel<<<NGRID, 256, CONV_SMEM>>>(conv_w, x);
    itrans_kernel<<<(2048 * NTIL + 255) / 256, 256>>>(conv_b);
    transpose_kernel<<<dim3(64, 25), dim3(32, 8)>>>();
    heads_kernel<<<98, 256>>>(reg_w, reg_b, cls_w, cls_b);
    scan_gather_kernel<<<1, 1024>>>(out);
}

// round 17
// speedup vs baseline: 1.0543x; 1.0543x over previous
#include <cuda_runtime.h>
#include <cuda_fp16.h>
#include <math.h>
#include <stdint.h>

// ---------------------------------------------------------------------------
// RPN round 17: Winograd F(4x4,3x3) + split-fp16 HMMA (R12 structure).
//  R17: GEMM uses 128-thread CTAs, 4 warps, warp tile 32x56, B fragments
//  paired into ldsm4 -> 12 LDSM per 42 MMA per warp per k16 (was 16/21).
//  2 CTAs/SM (95KB smem), split-K2, 2-stage pipeline (R12-verified order).
// ---------------------------------------------------------------------------

#define NPIX  784
#define NT7   7
#define NTIL  49
#define NTP   56
#define NPOS  36
#define KDIM  2048
#define KC    64
#define NCHH  16               // chunks per K-slice (K=1024)
#define TM    128
#define TN    56
#define NSTG  2
#define A_BYTES (TM * 128)     // 16384
#define B_BYTES (TN * 128)     // 7168
#define STG_SZ  (2 * A_BYTES + 2 * B_BYTES)   // 47104
#define CONV_SMEM (NSTG * STG_SZ + 1024)      // 95232
#define OFF_AH  0
#define OFF_AL  A_BYTES
#define OFF_BH  (2 * A_BYTES)
#define OFF_BL  (2 * A_BYTES + B_BYTES)

#define USTRIDE (2048 * 2048)
#define VSTRIDE (NTP * 2048)
#define MSTRIDE (2048 * NTP)

__device__ __half g_Uhi[NPOS * USTRIDE];
__device__ __half g_Ulo[NPOS * USTRIDE];
__device__ __half g_Vhi[NPOS * VSTRIDE];
__device__ __half g_Vlo[NPOS * VSTRIDE];
__device__ float  g_m[2][NPOS * MSTRIDE];
__device__ float  g_h[2048 * NPIX];
__device__ float  g_ht[NPIX * 2048];
__device__ float  g_head[45 * NPIX];

#define SWZ(o) ((uint32_t)(o) ^ ((((uint32_t)(o)) >> 3) & 0x70u))

__device__ __forceinline__ uint32_t smem_u32(const void* p) {
    uint32_t a;
    asm("{ .reg .u64 t; cvta.to.shared.u64 t, %1; cvt.u32.u64 %0, t; }"
        : "=r"(a) : "l"(p));
    return a;
}
__device__ __forceinline__ void cpa16(uint32_t dst, const void* src) {
    asm volatile("cp.async.cg.shared.global [%0], [%1], 16;"
                 :: "r"(dst), "l"(src) : "memory");
}
__device__ __forceinline__ void ldsm4(uint32_t* r, uint32_t addr) {
    asm volatile("ldmatrix.sync.aligned.m8n8.x4.shared.b16 {%0,%1,%2,%3}, [%4];"
                 : "=r"(r[0]), "=r"(r[1]), "=r"(r[2]), "=r"(r[3]) : "r"(addr));
}
__device__ __forceinline__ void ldsm2(uint32_t* r, uint32_t addr) {
    asm volatile("ldmatrix.sync.aligned.m8n8.x2.shared.b16 {%0,%1}, [%2];"
                 : "=r"(r[0]), "=r"(r[1]) : "r"(addr));
}
__device__ __forceinline__ void mma16816(float* d, const uint32_t* a, const uint32_t* b) {
    asm volatile(
        "mma.sync.aligned.m16n8k16.row.col.f32.f16.f16.f32 "
        "{%0,%1,%2,%3}, {%4,%5,%6,%7}, {%8,%9}, {%0,%1,%2,%3};"
        : "+f"(d[0]), "+f"(d[1]), "+f"(d[2]), "+f"(d[3])
        : "r"(a[0]), "r"(a[1]), "r"(a[2]), "r"(a[3]), "r"(b[0]), "r"(b[1]));
}
__device__ __forceinline__ ushort hi_part(float v, float& rem) {
    __half h = __float2half_rn(v);
    rem = v - __half2float(h);
    return *(ushort*)&h;
}

// ----------------- weight transform: U = G g G^T ---------------------------
__global__ __launch_bounds__(256) void wtrans_kernel(const float* __restrict__ W) {
    int q = blockIdx.x * blockDim.x + threadIdx.x;
    const int nq = (2048 * 2048) / 4;
    if (q >= nq) return;
    const int t0 = q * 4;

    float f[36];
    {
        const float4* w4 = (const float4*)(W + (size_t)t0 * 9);
        #pragma unroll
        for (int k = 0; k < 9; k++) {
            float4 v = __ldg(&w4[k]);
            f[4 * k + 0] = v.x; f[4 * k + 1] = v.y;
            f[4 * k + 2] = v.z; f[4 * k + 3] = v.w;
        }
    }

    const float c6 = 1.f / 6.f, c12 = 1.f / 12.f, c24 = 1.f / 24.f;
    ushort uhi[36][4], ulo[36][4];
    #pragma unroll
    for (int j = 0; j < 4; j++) {
        const float* g = f + j * 9;
        float T[6][3];
        #pragma unroll
        for (int cc = 0; cc < 3; cc++) {
            float a = g[cc], b = g[3 + cc], d = g[6 + cc];
            T[0][cc] = 0.25f * a;
            T[1][cc] = -c6 * (a + b + d);
            T[2][cc] = c6 * (-a + b - d);
            T[3][cc] = c24 * a + c12 * b + c6 * d;
            T[4][cc] = c24 * a - c12 * b + c6 * d;
            T[5][cc] = d;
        }
        #pragma unroll
        for (int i = 0; i < 6; i++) {
            float a = T[i][0], b = T[i][1], d = T[i][2];
            float u[6];
            u[0] = 0.25f * a;
            u[1] = -c6 * (a + b + d);
            u[2] = c6 * (-a + b - d);
            u[3] = c24 * a + c12 * b + c6 * d;
            u[4] = c24 * a - c12 * b + c6 * d;
            u[5] = d;
            #pragma unroll
            for (int cc = 0; cc < 6; cc++) {
                float rem;
                uhi[6 * i + cc][j] = hi_part(u[cc], rem);
                __half lo = __float2half_rn(rem);
                ulo[6 * i + cc][j] = *(ushort*)&lo;
            }
        }
    }
    #pragma unroll
    for (int p = 0; p < 36; p++) {
        *(uint2*)(g_Uhi + (size_t)p * USTRIDE + t0) = *(uint2*)uhi[p];
        *(uint2*)(g_Ulo + (size_t)p * USTRIDE + t0) = *(uint2*)ulo[p];
    }
}

// ----------------- input transform: V = B^T d B ----------------------------
__global__ __launch_bounds__(256) void xtrans_kernel(const float* __restrict__ X) {
    int q = blockIdx.x * blockDim.x + threadIdx.x;
    const int nq = (NTP * 2048) / 4;
    if (q >= nq) return;
    const int t0 = q * 4;
    const int tile = t0 >> 11;
    const int ic0 = t0 & 2047;

    if (tile >= NTIL) {
        #pragma unroll
        for (int p = 0; p < 36; p++) {
            *(uint2*)(g_Vhi + (size_t)p * VSTRIDE + t0) = make_uint2(0u, 0u);
            *(uint2*)(g_Vlo + (size_t)p * VSTRIDE + t0) = make_uint2(0u, 0u);
        }
        return;
    }
    const int ti = tile / NT7, tj = tile - ti * NT7;

    ushort dhi[36][4], dlo[36][4];
    #pragma unroll
    for (int j = 0; j < 4; j++) {
        const float* xp = X + (size_t)(ic0 + j) * NPIX;
        float d[6][6];
        #pragma unroll
        for (int r = 0; r < 6; r++) {
            int yy = 4 * ti - 1 + r;
            #pragma unroll
            for (int cq = 0; cq < 6; cq++) {
                int xx = 4 * tj - 1 + cq;
                d[r][cq] = ((unsigned)yy < 28u && (unsigned)xx < 28u)
                           ? __ldg(&xp[yy * 28 + xx]) : 0.f;
            }
        }
        float T[6][6];
        #pragma unroll
        for (int c = 0; c < 6; c++) {
            T[0][c] = 4.f * d[0][c] - 5.f * d[2][c] + d[4][c];
            T[1][c] = -4.f * d[1][c] - 4.f * d[2][c] + d[3][c] + d[4][c];
            T[2][c] = 4.f * d[1][c] - 4.f * d[2][c] - d[3][c] + d[4][c];
            T[3][c] = -2.f * d[1][c] - d[2][c] + 2.f * d[3][c] + d[4][c];
            T[4][c] = 2.f * d[1][c] - d[2][c] - 2.f * d[3][c] + d[4][c];
            T[5][c] = 4.f * d[1][c] - 5.f * d[3][c] + d[5][c];
        }
        #pragma unroll
        for (int i = 0; i < 6; i++) {
            float v[6];
            v[0] = 4.f * T[i][0] - 5.f * T[i][2] + T[i][4];
            v[1] = -4.f * T[i][1] - 4.f * T[i][2] + T[i][3] + T[i][4];
            v[2] = 4.f * T[i][1] - 4.f * T[i][2] - T[i][3] + T[i][4];
            v[3] = -2.f * T[i][1] - T[i][2] + 2.f * T[i][3] + T[i][4];
            v[4] = 2.f * T[i][1] - T[i][2] - 2.f * T[i][3] + T[i][4];
            v[5] = 4.f * T[i][1] - 5.f * T[i][3] + T[i][5];
            #pragma unroll
            for (int cc = 0; cc < 6; cc++) {
                float rem;
                dhi[6 * i + cc][j] = hi_part(v[cc], rem);
                __half lo = __float2half_rn(rem);
                dlo[6 * i + cc][j] = *(ushort*)&lo;
            }
        }
    }
    #pragma unroll
    for (int p = 0; p < 36; p++) {
        *(uint2*)(g_Vhi + (size_t)p * VSTRIDE + t0) = *(uint2*)dhi[p];
        *(uint2*)(g_Vlo + (size_t)p * VSTRIDE + t0) = *(uint2*)dlo[p];
    }
}

// --------------- Winograd GEMM (128 thr, 4 warps of 32x56) -----------------
// grid (16, 72): x = M tile, y = pos*2 + kslice.  2 CTAs/SM.
__global__ __launch_bounds__(128, 2) void wino_mma_kernel() {
    extern __shared__ char smraw[];
    uintptr_t basep = ((uintptr_t)smraw + 1023) & ~(uintptr_t)1023;
    const uint32_t smb = smem_u32((void*)basep);

    const int tid  = threadIdx.x;
    const int wid  = tid >> 5;
    const int lane = tid & 31;
    const int m0   = blockIdx.x * TM;
    const int pos  = blockIdx.y >> 1;
    const int ksl  = blockIdx.y & 1;
    const int kbase = ksl * (NCHH * KC);
    const int wm   = wid * 32;

    const __half* Ahi = g_Uhi + (size_t)pos * USTRIDE;
    const __half* Alo = g_Ulo + (size_t)pos * USTRIDE;
    const __half* Bhi = g_Vhi + (size_t)pos * VSTRIDE;
    const __half* Blo = g_Vlo + (size_t)pos * VSTRIDE;

    uint32_t aoff[2], boffp[3], boff6;
    {
        int arow = wm + (lane & 15);
        int acol = (lane >> 4) * 16;
        #pragma unroll
        for (int mt = 0; mt < 2; mt++)
            aoff[mt] = SWZ((arow + mt * 16) * 128 + acol);
        // paired ldsm4: covers n-tiles (2t, 2t+1), rows t*16 .. t*16+15
        int brow = ((lane >> 4) & 1) * 8 + (lane & 7);
        int bcol = ((lane >> 3) & 1) * 16;
        #pragma unroll
        for (int t = 0; t < 3; t++)
            boffp[t] = SWZ((brow + t * 16) * 128 + bcol);
        // tail n-tile 6 (rows 48..55): ldsm2 mapping
        int bi = lane & 15;
        boff6 = SWZ((48 + (bi & 7)) * 128 + ((bi >> 3) & 1) * 16);
    }

    float acc[2][7][4];
    #pragma unroll
    for (int mt = 0; mt < 2; mt++)
        #pragma unroll
        for (int nt = 0; nt < 7; nt++)
            #pragma unroll
            for (int i = 0; i < 4; i++) acc[mt][nt][i] = 0.f;

    auto load_stage = [&](int it) {
        const int stg = it % NSTG;
        const uint32_t sb = smb + stg * STG_SZ;
        const int kc = kbase + it * KC;
        #pragma unroll
        for (int q = tid; q < 1024; q += 128) {          // A: 128 rows x 8
            int r = q >> 3, c = q & 7;
            uint32_t so = SWZ(r * 128 + c * 16);
            size_t go = (size_t)(m0 + r) * KDIM + kc + c * 8;
            cpa16(sb + OFF_AH + so, Ahi + go);
            cpa16(sb + OFF_AL + so, Alo + go);
        }
        for (int q = tid; q < 448; q += 128) {           // B: 56 rows x 8
            int r = q >> 3, c = q & 7;
            uint32_t so = SWZ(r * 128 + c * 16);
            size_t go = (size_t)r * KDIM + kc + c * 8;
            cpa16(sb + OFF_BH + so, Bhi + go);
            cpa16(sb + OFF_BL + so, Blo + go);
        }
    };

    load_stage(0);
    asm volatile("cp.async.commit_group;" ::: "memory");

    for (int c = 0; c < NCHH; ++c) {
        if (c > 0) __syncthreads();          // prev compute done before reuse
        if (c + 1 < NCHH) {
            load_stage(c + 1);
            asm volatile("cp.async.commit_group;" ::: "memory");
            asm volatile("cp.async.wait_group 1;" ::: "memory");
        } else {
            asm volatile("cp.async.wait_group 0;" ::: "memory");
        }
        __syncthreads();

        const uint32_t sb = smb + (c % NSTG) * STG_SZ;
        #pragma unroll
        for (int kk = 0; kk < 4; kk++) {
            const uint32_t kd = kk * 32;
            uint32_t ah[2][4], al[2][4], bh[7][2], bl[7][2];
            #pragma unroll
            for (int mt = 0; mt < 2; mt++) {
                ldsm4(ah[mt], sb + OFF_AH + (aoff[mt] ^ kd));
                ldsm4(al[mt], sb + OFF_AL + (aoff[mt] ^ kd));
            }
            #pragma unroll
            for (int t = 0; t < 3; t++) {
                uint32_t tmp[4];
                ldsm4(tmp, sb + OFF_BH + (boffp[t] ^ kd));
                bh[2 * t][0] = tmp[0]; bh[2 * t][1] = tmp[1];
                bh[2 * t + 1][0] = tmp[2]; bh[2 * t + 1][1] = tmp[3];
                ldsm4(tmp, sb + OFF_BL + (boffp[t] ^ kd));
                bl[2 * t][0] = tmp[0]; bl[2 * t][1] = tmp[1];
                bl[2 * t + 1][0] = tmp[2]; bl[2 * t + 1][1] = tmp[3];
            }
            ldsm2(bh[6], sb + OFF_BH + (boff6 ^ kd));
            ldsm2(bl[6], sb + OFF_BL + (boff6 ^ kd));
            #pragma unroll
            for (int mt = 0; mt < 2; mt++)
                #pragma unroll
                for (int nt = 0; nt < 7; nt++) {
                    mma16816(acc[mt][nt], ah[mt], bh[nt]);
                    mma16816(acc[mt][nt], ah[mt], bl[nt]);
                    mma16816(acc[mt][nt], al[mt], bh[nt]);
                }
        }
    }

    const int l4 = lane >> 2;
    const int l2 = (lane & 3) * 2;
    float* mdst = g_m[ksl] + (size_t)pos * MSTRIDE;
    #pragma unroll
    for (int mt = 0; mt < 2; mt++) {
        int ocA = m0 + wm + mt * 16 + l4;
        int ocB = ocA + 8;
        #pragma unroll
        for (int nt = 0; nt < 7; nt++) {
            int col = nt * 8 + l2;
            float2 vA, vB;
            vA.x = acc[mt][nt][0]; vA.y = acc[mt][nt][1];
            vB.x = acc[mt][nt][2]; vB.y = acc[mt][nt][3];
            *(float2*)(mdst + (size_t)ocA * NTP + col) = vA;
            *(float2*)(mdst + (size_t)ocB * NTP + col) = vB;
        }
    }
}

// ------------------- inverse transform: y = A^T m A + bias, relu -----------
__global__ __launch_bounds__(256) void itrans_kernel(const float* __restrict__ CB) {
    int t = blockIdx.x * blockDim.x + threadIdx.x;
    if (t >= 2048 * NTIL) return;
    int oc = t / NTIL;
    int tile = t - oc * NTIL;
    int ti = tile / NT7, tj = tile - ti * NT7;

    float m[36];
    #pragma unroll
    for (int p = 0; p < 36; p++) {
        size_t off = (size_t)p * MSTRIDE + (size_t)oc * NTP + tile;
        m[p] = g_m[0][off] + g_m[1][off];
    }

    float T[4][6];
    #pragma unroll
    for (int c = 0; c < 6; c++) {
        float m0 = m[c], m1 = m[6 + c], m2 = m[12 + c];
        float m3 = m[18 + c], m4 = m[24 + c], m5 = m[30 + c];
        T[0][c] = m0 + m1 + m2 + m3 + m4;
        T[1][c] = m1 - m2 + 2.f * (m3 - m4);
        T[2][c] = m1 + m2 + 4.f * (m3 + m4);
        T[3][c] = m1 - m2 + 8.f * (m3 - m4) + m5;
    }

    float bias = __ldg(&CB[oc]);
    float* hp = g_h + (size_t)oc * NPIX;
    int oy = 4 * ti, ox = 4 * tj;
    #pragma unroll
    for (int i = 0; i < 4; i++) {
        float t0 = T[i][0], t1 = T[i][1], t2 = T[i][2];
        float t3 = T[i][3], t4 = T[i][4], t5 = T[i][5];
        float y0 = t0 + t1 + t2 + t3 + t4;
        float y1 = t1 - t2 + 2.f * (t3 - t4);
        float y2 = t1 + t2 + 4.f * (t3 + t4);
        float y3 = t1 - t2 + 8.f * (t3 - t4) + t5;
        hp[(oy + i) * 28 + ox + 0] = fmaxf(y0 + bias, 0.f);
        hp[(oy + i) * 28 + ox + 1] = fmaxf(y1 + bias, 0.f);
        hp[(oy + i) * 28 + ox + 2] = fmaxf(y2 + bias, 0.f);
        hp[(oy + i) * 28 + ox + 3] = fmaxf(y3 + bias, 0.f);
    }
}

// --------------------- transpose g_h[ch][pix] -> g_ht[pix][ch] -------------
__global__ void transpose_kernel() {
    __shared__ float ts[32][33];
    int cb = blockIdx.x * 32;
    int pb = blockIdx.y * 32;
    int tx = threadIdx.x, ty = threadIdx.y;
    #pragma unroll
    for (int j = 0; j < 4; j++) {
        int ch = cb + ty + j * 8;
        int p = pb + tx;
        if (p < NPIX) ts[ty + j * 8][tx] = g_h[(size_t)ch * NPIX + p];
    }
    __syncthreads();
    #pragma unroll
    for (int j = 0; j < 4; j++) {
        int p = pb + ty + j * 8;
        int ch = cb + tx;
        if (p < NPIX) g_ht[(size_t)p * 2048 + ch] = ts[tx][ty + j * 8];
    }
}

// ------------------------------- heads -------------------------------------
__global__ __launch_bounds__(256) void heads_kernel(
    const float* __restrict__ reg_w, const float* __restrict__ reg_b,
    const float* __restrict__ cls_w, const float* __restrict__ cls_b)
{
    const int lane = threadIdx.x & 31;
    const int warp = threadIdx.x >> 5;
    const int p = blockIdx.x * 8 + warp;

    float4 hv[16];
    #pragma unroll
    for (int j = 0; j < 16; j++)
        hv[j] = __ldg((const float4*)(g_ht + (size_t)p * 2048 + lane * 4 + 128 * j));

    #pragma unroll 1
    for (int o = 0; o < 45; o++) {
        const float* w = (o < 36) ? (reg_w + o * 2048) : (cls_w + (o - 36) * 2048);
        float s = 0.f;
        #pragma unroll
        for (int j = 0; j < 16; j++) {
            float4 wq = __ldg((const float4*)(w + lane * 4 + 128 * j));
            s += hv[j].x * wq.x + hv[j].y * wq.y + hv[j].z * wq.z + hv[j].w * wq.w;
        }
        #pragma unroll
        for (int off = 16; off > 0; off >>= 1) s += __shfl_xor_sync(0xffffffffu, s, off);
        if (lane == 0) {
            float b = (o < 36) ? __ldg(&reg_b[o]) : __ldg(&cls_b[o - 36]);
            g_head[o * NPIX + p] = 1.f / (1.f + expf(-(s + b)));
        }
    }
}

// ------------------------- scan + gather (fused) ---------------------------
__device__ __forceinline__ bool anchor_valid(int j) {
    int a = j % 9, p = j / 9;
    int y = p / 28, x = p % 28;
    double scale = (a / 3 == 0) ? 64.0 : (a / 3 == 1) ? 128.0 : 256.0;
    double ratio = (a % 3 == 0) ? 0.5 : (a % 3 == 1) ? 1.0 : 2.0;
    double hh = scale / sqrt(ratio) / 448.0;
    double ww = scale * sqrt(ratio) / 448.0;
    double cy = ((double)y + 0.5) / 28.0;
    double cx = ((double)x + 0.5) / 28.0;
    double y1 = cy - hh / 2.0, x1 = cx - ww / 2.0;
    double y2 = cy + hh / 2.0, x2 = cx + ww / 2.0;
    return (y1 > 0.0) && (x1 > 0.0) && (y2 < 28.0) && (x2 < 28.0);
}

__global__ void scan_gather_kernel(float* __restrict__ out) {
    __shared__ int s[1024];
    const int tid = threadIdx.x;
    const int base = tid * 7;
    int f[7];
    int cnt = 0;
    #pragma unroll
    for (int i = 0; i < 7; i++) {
        int j = base + i;
        f[i] = (j < 7056 && anchor_valid(j)) ? 1 : 0;
        cnt += f[i];
    }
    s[tid] = cnt;
    __syncthreads();
    for (int off = 1; off < 1024; off <<= 1) {
        int v = s[tid];
        int add = (tid >= off) ? s[tid - off] : 0;
        __syncthreads();
        s[tid] = v + add;
        __syncthreads();
    }
    int pos = s[tid] - cnt;
    #pragma unroll
    for (int i = 0; i < 7; i++) {
        int j = base + i;
        if (j < 7056 && f[i]) {
            int a = j / NPIX, p = j % NPIX;
            float cls = g_head[(36 + a) * NPIX + p];
            float k = (cls > 0.9f) ? 1.f : 0.f;
            #pragma unroll
            for (int c = 0; c < 4; c++)
                out[pos * 4 + c] = g_head[(c * 9 + a) * NPIX + p] * k;
            pos++;
        }
    }
}

// ---------------------------------------------------------------------------
extern "C" void kernel_launch(void* const* d_in, const int* in_sizes, int n_in,
                              void* d_out, int out_size)
{
    const float* x      = (const float*)d_in[0];
    const float* conv_w = (const float*)d_in[1];
    const float* conv_b = (const float*)d_in[2];
    const float* reg_w  = (const float*)d_in[3];
    const float* reg_b  = (const float*)d_in[4];
    const float* cls_w  = (const float*)d_in[5];
    const float* cls_b  = (const float*)d_in[6];
    float* out = (float*)d_out;

    cudaFuncSetAttribute(wino_mma_kernel,
                         cudaFuncAttributeMaxDynamicSharedMemorySize, CONV_SMEM);

    wtrans_kernel<<<(2048 * 2048 / 4 + 255) / 256, 256>>>(conv_w);
    xtrans_kernel<<<(NTP * 2048 / 4 + 255) / 256, 256>>>(x);
    wino_mma_kernel<<<dim3(16, NPOS * 2), 128, CONV_SMEM>>>();
    itrans_kernel<<<(2048 * NTIL + 255) / 256, 256>>>(conv_b);
    transpose_kernel<<<dim3(64, 25), dim3(32, 8)>>>();
    heads_kernel<<<98, 256>>>(reg_w, reg_b, cls_w, cls_b);
    scan_gather_kernel<<<1, 1024>>>(out);
}